// round 14
// baseline (speedup 1.0000x reference)
#include <cuda_runtime.h>
#include <cuda_bf16.h>
#include <cstdint>
#include <cstddef>

#define BB 16384   // batch
#define NF 512     // features
#define NU 256     // used features
#define NL 1024    // leaves / decision node slots
#define NC 100     // classes
#define NCP 128    // classes padded

// -------- device scratch (static; no allocations anywhere) --------
__device__ int            g_idx[NU];
__device__ __nv_bfloat16  g_xb[(size_t)BB * NU];
__device__ __nv_bfloat16  g_Wb[(size_t)NU * NL];    // W bf16, [k][n]
__device__ __nv_bfloat16  g_probs[(size_t)NL * NCP];
__device__ __nv_bfloat16  g_d[(size_t)BB * NL];

// -------- cp.async helpers --------
__device__ __forceinline__ void cpa16(void* smem, const void* gmem) {
    uint32_t s = (uint32_t)__cvta_generic_to_shared(smem);
    asm volatile("cp.async.cg.shared.global [%0], [%1], 16;\n" :: "r"(s), "l"(gmem));
}
__device__ __forceinline__ void cpa_commit() { asm volatile("cp.async.commit_group;\n" ::: "memory"); }
template<int N> __device__ __forceinline__ void cpa_wait() { asm volatile("cp.async.wait_group %0;\n" :: "n"(N) : "memory"); }

// -------- ldmatrix / mma.sync helpers --------
__device__ __forceinline__ void ldsm_x4(uint32_t addr, uint32_t& r0, uint32_t& r1,
                                        uint32_t& r2, uint32_t& r3) {
    asm volatile("ldmatrix.sync.aligned.m8n8.x4.shared.b16 {%0,%1,%2,%3}, [%4];"
                 : "=r"(r0), "=r"(r1), "=r"(r2), "=r"(r3) : "r"(addr));
}
__device__ __forceinline__ void ldsm_x4_t(uint32_t addr, uint32_t& r0, uint32_t& r1,
                                          uint32_t& r2, uint32_t& r3) {
    asm volatile("ldmatrix.sync.aligned.m8n8.x4.trans.shared.b16 {%0,%1,%2,%3}, [%4];"
                 : "=r"(r0), "=r"(r1), "=r"(r2), "=r"(r3) : "r"(addr));
}
__device__ __forceinline__ void mma16816(float* c, uint32_t a0, uint32_t a1, uint32_t a2,
                                         uint32_t a3, uint32_t b0, uint32_t b1) {
    asm volatile("mma.sync.aligned.m16n8k16.row.col.f32.bf16.bf16.f32 "
                 "{%0,%1,%2,%3}, {%4,%5,%6,%7}, {%8,%9}, {%0,%1,%2,%3};"
                 : "+f"(c[0]), "+f"(c[1]), "+f"(c[2]), "+f"(c[3])
                 : "r"(a0), "r"(a1), "r"(a2), "r"(a3), "r"(b0), "r"(b1));
}

// -------- coalesced gather: 4 rows/block via SMEM staging --------
__global__ __launch_bounds__(256) void k_gather(const float* __restrict__ feat) {
    __shared__ float rows[4][NF];
    __shared__ int sidx[NU];
    int t = threadIdx.x;
    sidx[t] = g_idx[t];
    int row0 = blockIdx.x * 4;
    const float4* src = reinterpret_cast<const float4*>(feat + (size_t)row0 * NF);
    float4* dst4 = reinterpret_cast<float4*>(&rows[0][0]);
    dst4[t] = src[t];
    dst4[t + 256] = src[t + 256];
    __syncthreads();
#pragma unroll
    for (int r = 0; r < 4; r++)
        g_xb[(size_t)(row0 + r) * NU + t] = __float2bfloat16(rows[r][sidx[t]]);
}

// -------- merged prep: 0..255 W conv | 256..383 softmax(pi) | 384..639 idx --------
__global__ __launch_bounds__(256) void k_prep(const float* __restrict__ W,
                                              const float* __restrict__ pi,
                                              const float* __restrict__ mask) {
    int b = blockIdx.x;
    if (b < 256) {
        int i = b * 256 + threadIdx.x;
        float4 v = reinterpret_cast<const float4*>(W)[i];
        __nv_bfloat162 p0 = __floats2bfloat162_rn(v.x, v.y);
        __nv_bfloat162 p1 = __floats2bfloat162_rn(v.z, v.w);
        uint2 u;
        u.x = *reinterpret_cast<unsigned*>(&p0);
        u.y = *reinterpret_cast<unsigned*>(&p1);
        reinterpret_cast<uint2*>(g_Wb)[i] = u;
    } else if (b < 384) {
        int w = (b - 256) * 8 + (threadIdx.x >> 5);
        int lane = threadIdx.x & 31;
        const float* row = pi + (size_t)w * NC;
        float4 v;
        if (lane < 25) v = reinterpret_cast<const float4*>(row)[lane];
        else v = make_float4(-1e30f, -1e30f, -1e30f, -1e30f);
        float m = fmaxf(fmaxf(v.x, v.y), fmaxf(v.z, v.w));
#pragma unroll
        for (int o = 16; o > 0; o >>= 1) m = fmaxf(m, __shfl_xor_sync(0xffffffffu, m, o));
        float e0 = (lane < 25) ? expf(v.x - m) : 0.f;
        float e1 = (lane < 25) ? expf(v.y - m) : 0.f;
        float e2 = (lane < 25) ? expf(v.z - m) : 0.f;
        float e3 = (lane < 25) ? expf(v.w - m) : 0.f;
        float s = e0 + e1 + e2 + e3;
#pragma unroll
        for (int o = 16; o > 0; o >>= 1) s += __shfl_xor_sync(0xffffffffu, s, o);
        float inv = 1.f / s;
        __nv_bfloat162 p0 = __floats2bfloat162_rn(e0 * inv, e1 * inv);
        __nv_bfloat162 p1 = __floats2bfloat162_rn(e2 * inv, e3 * inv);
        uint2 u;
        u.x = *reinterpret_cast<unsigned*>(&p0);
        u.y = *reinterpret_cast<unsigned*>(&p1);
        reinterpret_cast<uint2*>(g_probs + (size_t)w * NCP)[lane] = u;
    } else {
        int j = b - 384;                 // used-feature index
        int t = threadIdx.x;
        if (t < 128) {
            float4 v = reinterpret_cast<const float4*>(mask + (size_t)j * NF)[t];
            int f = -1;
            if      (v.x > 0.5f) f = 4 * t;
            else if (v.y > 0.5f) f = 4 * t + 1;
            else if (v.z > 0.5f) f = 4 * t + 2;
            else if (v.w > 0.5f) f = 4 * t + 3;
            if (f >= 0) g_idx[j] = f;
        }
    }
}

// -------- GEMM1: d = sigmoid(xb @ Wb + b)  [16384x1024x256]
// 128 threads, 128x128 tile, warp tile 64x64 (2m x 2n), BK=64, 3-stage cp.async.
// Register-fat: acc=128/thread; ILP (32 indep mma per kk) hides ldsm latency.
#define G1_AS 72    // A smem row stride (bf16): 144 B, conflict-free for ldsm
#define G1_BS 136   // B smem row stride (bf16): 272 B
#define G1_A_BYTES (128 * G1_AS * 2)   // 18432 per stage
#define G1_B_BYTES (64 * G1_BS * 2)    // 17408 per stage
#define G1_SMEM (3 * (G1_A_BYTES + G1_B_BYTES))   // 107520
__global__ __launch_bounds__(128, 2) void k_gemm1(const float* __restrict__ bias) {
    extern __shared__ __align__(16) unsigned char smem[];
    __nv_bfloat16* As = reinterpret_cast<__nv_bfloat16*>(smem);                  // 3 x 128x72
    __nv_bfloat16* Bs = reinterpret_cast<__nv_bfloat16*>(smem + 3 * G1_A_BYTES); // 3 x 64x136
    uint32_t sbase = (uint32_t)__cvta_generic_to_shared(smem);
    uint32_t sA = sbase;
    uint32_t sB = sbase + 3 * G1_A_BYTES;

    int tid = threadIdx.x, wid = tid >> 5, lane = tid & 31;
    int wm = wid & 1, wn = wid >> 1;           // 2(m) x 2(n), warp tile 64x64
    int n0 = blockIdx.x * 128, row0 = blockIdx.y * 128;

    float acc[4][8][4];
#pragma unroll
    for (int i = 0; i < 4; i++)
#pragma unroll
        for (int j = 0; j < 8; j++)
#pragma unroll
            for (int q = 0; q < 4; q++) acc[i][j][q] = 0.f;

    auto load_stage = [&](int st, int ko) {
        __nv_bfloat16* a = As + st * 128 * G1_AS;
        __nv_bfloat16* b = Bs + st * 64 * G1_BS;
#pragma unroll
        for (int s = tid; s < 1024; s += 128) {         // A: 128 x 64 (8/thread)
            int r = s >> 3, c = (s & 7) * 8;
            cpa16(a + r * G1_AS + c, g_xb + (size_t)(row0 + r) * NU + ko + c);
        }
#pragma unroll
        for (int s = tid; s < 1024; s += 128) {         // B: 64 x 128 (8/thread)
            int r = s >> 4, c = (s & 15) * 8;
            cpa16(b + r * G1_BS + c, g_Wb + (size_t)(ko + r) * NL + n0 + c);
        }
        cpa_commit();
    };

    int lrow = lane & 15;
    int lk8  = (lane >> 4) << 3;
    uint32_t aOff = (uint32_t)((wm * 64 + lrow) * G1_AS + lk8) * 2;   // + i*16 rows
    uint32_t bOff = (uint32_t)(lrow * G1_BS + wn * 64 + lk8) * 2;     // + jj*16 cols

    // prologue: 2 chunks in flight, wait for chunk 0
    load_stage(0, 0);
    load_stage(1, 64);
    cpa_wait<1>();
    __syncthreads();

    const int NCH = NU / 64;   // 4
    for (int ch = 0; ch < NCH; ch++) {           // NOT unrolled: keeps code size sane
        if (ch + 2 < NCH) load_stage((ch + 2) % 3, (ch + 2) * 64);

        uint32_t aSt = sA + (ch % 3) * G1_A_BYTES + aOff;
        uint32_t bSt = sB + (ch % 3) * G1_B_BYTES + bOff;
#pragma unroll
        for (int kk = 0; kk < 4; kk++) {
            uint32_t a[4][4];
#pragma unroll
            for (int i = 0; i < 4; i++)
                ldsm_x4(aSt + kk * 32 + i * (16 * G1_AS * 2),
                        a[i][0], a[i][1], a[i][2], a[i][3]);
#pragma unroll
            for (int jj = 0; jj < 4; jj++) {            // 4 trans ldsm cover 64 cols
                uint32_t t[4];
                ldsm_x4_t(bSt + kk * (16 * G1_BS * 2) + jj * 32, t[0], t[1], t[2], t[3]);
#pragma unroll
                for (int i = 0; i < 4; i++) {
                    mma16816(acc[i][2 * jj],     a[i][0], a[i][1], a[i][2], a[i][3], t[0], t[1]);
                    mma16816(acc[i][2 * jj + 1], a[i][0], a[i][1], a[i][2], a[i][3], t[2], t[3]);
                }
            }
        }
        if (ch + 1 < NCH) {
            if (ch + 2 < NCH) cpa_wait<1>();
            else              cpa_wait<0>();
            __syncthreads();
        }
    }

    // direct epilogue: bias + sigmoid from fragments -> g_d bf16x2 stores
    int erow = lane >> 2;            // 0..7
    int ecol = 2 * (lane & 3);       // 0,2,4,6
#pragma unroll
    for (int i = 0; i < 4; i++) {
#pragma unroll
        for (int j = 0; j < 8; j++) {
            int cbase = n0 + wn * 64 + j * 8 + ecol;
            float b0 = bias[cbase], b1 = bias[cbase + 1];
            int r_lo = row0 + wm * 64 + i * 16 + erow;
            float z0 = acc[i][j][0] + b0, z1 = acc[i][j][1] + b1;
            __nv_bfloat162 p0 = __floats2bfloat162_rn(1.f / (1.f + __expf(-z0)),
                                                      1.f / (1.f + __expf(-z1)));
            *reinterpret_cast<__nv_bfloat162*>(g_d + (size_t)r_lo * NL + cbase) = p0;
            float z2 = acc[i][j][2] + b0, z3 = acc[i][j][3] + b1;
            __nv_bfloat162 p1 = __floats2bfloat162_rn(1.f / (1.f + __expf(-z2)),
                                                      1.f / (1.f + __expf(-z3)));
            *reinterpret_cast<__nv_bfloat162*>(g_d + (size_t)(r_lo + 8) * NL + cbase) = p1;
        }
    }
}

// -------- fused tree-product + GEMM2: out = mu(d) @ probs  [16384x128x1024]
// (unchanged round-11 version, measured inside 92.2us) Prefix-only SMEM;
// levels 7-9 streamed from L2. 3-stage As/Bs, 1 barrier/iter, 256 threads,
// 64-row block, BK=32, raw mma, 2(m)x4(n) warps, warp tile 32x32.
#define F2_PS 136
#define F2_P_BYTES (64 * F2_PS * 2)      // 17408
#define F2_BS 136
#define F2_B_BYTES (32 * F2_BS * 2)      // 8704 per stage
#define F2_AS 40
#define F2_A_BYTES (64 * F2_AS * 2)      // 5120 per stage
#define F2_SMEM (F2_P_BYTES + 3 * F2_B_BYTES + 3 * F2_A_BYTES)   // 58880
__global__ __launch_bounds__(256, 3) void k_fused2(float* __restrict__ out) {
    extern __shared__ __align__(16) unsigned char smem[];
    __nv_bfloat16* dpre = reinterpret_cast<__nv_bfloat16*>(smem);
    __nv_bfloat16* Bs   = reinterpret_cast<__nv_bfloat16*>(smem + F2_P_BYTES);
    __nv_bfloat16* As   = reinterpret_cast<__nv_bfloat16*>(smem + F2_P_BYTES + 3 * F2_B_BYTES);
    uint32_t sbase = (uint32_t)__cvta_generic_to_shared(smem);
    uint32_t sB = sbase + F2_P_BYTES;
    uint32_t sA = sB + 3 * F2_B_BYTES;

    int tid = threadIdx.x, wid = tid >> 5, lane = tid & 31;
    int wm = wid & 1, wn = wid >> 1;
    int row0 = blockIdx.x * 64;

    int mrow = tid >> 2, mgrp = tid & 3;
    const __nv_bfloat16* prow = dpre + mrow * F2_PS;
    const __nv_bfloat16* grow = g_d + (size_t)(row0 + mrow) * NL;

    float acc[2][4][4];
#pragma unroll
    for (int i = 0; i < 2; i++)
#pragma unroll
        for (int j = 0; j < 4; j++)
#pragma unroll
            for (int q = 0; q < 4; q++) acc[i][j][q] = 0.f;

    auto load_B = [&](int st, int ko) {
        __nv_bfloat16* b = Bs + st * 32 * F2_BS;
#pragma unroll
        for (int s = tid; s < 512; s += 256) {
            int r = s >> 4, c = (s & 15) * 8;
            cpa16(b + r * F2_BS + c, g_probs + (size_t)(ko + r) * NCP + c);
        }
        cpa_commit();
    };

    auto make_mu = [&](int st, int ch) {
        int h = ch * 4 + mgrp;
        float P = 1.f;
#pragma unroll
        for (int lev = 0; lev < 7; lev++) {
            int node = (1 << lev) + (h >> (7 - lev));
            int bit  = (h >> (6 - lev)) & 1;
            float dv = __bfloat162float(prow[node]);
            P *= bit ? (1.f - dv) : dv;
        }
        float d7 = __bfloat162float(grow[128 + h]);
        __nv_bfloat162 p8 = *reinterpret_cast<const __nv_bfloat162*>(grow + 256 + 2 * h);
        float d8a = __bfloat162float(__low2bfloat16(p8));
        float d8b = __bfloat162float(__high2bfloat16(p8));
        uint2 q9 = *reinterpret_cast<const uint2*>(grow + 512 + 4 * h);
        __nv_bfloat162 q9a = *reinterpret_cast<__nv_bfloat162*>(&q9.x);
        __nv_bfloat162 q9b = *reinterpret_cast<__nv_bfloat162*>(&q9.y);
        float d90 = __bfloat162float(__low2bfloat16(q9a));
        float d91 = __bfloat162float(__high2bfloat16(q9a));
        float d92 = __bfloat162float(__low2bfloat16(q9b));
        float d93 = __bfloat162float(__high2bfloat16(q9b));
        float pa = P * d7;
        float pb = P * (1.f - d7);
        float m0 = pa * d8a * d90;
        float m1 = pa * d8a * (1.f - d90);
        float m2 = pa * (1.f - d8a) * d91;
        float m3 = pa * (1.f - d8a) * (1.f - d91);
        float m4 = pb * d8b * d92;
        float m5 = pb * d8b * (1.f - d92);
        float m6 = pb * (1.f - d8b) * d93;
        float m7 = pb * (1.f - d8b) * (1.f - d93);
        __nv_bfloat162 o0 = __floats2bfloat162_rn(m0, m1);
        __nv_bfloat162 o1 = __floats2bfloat162_rn(m2, m3);
        __nv_bfloat162 o2 = __floats2bfloat162_rn(m4, m5);
        __nv_bfloat162 o3 = __floats2bfloat162_rn(m6, m7);
        uint4 u;
        u.x = *reinterpret_cast<unsigned*>(&o0);
        u.y = *reinterpret_cast<unsigned*>(&o1);
        u.z = *reinterpret_cast<unsigned*>(&o2);
        u.w = *reinterpret_cast<unsigned*>(&o3);
        *reinterpret_cast<uint4*>(As + st * 64 * F2_AS + mrow * F2_AS + mgrp * 8) = u;
    };

#pragma unroll
    for (int s = tid; s < 1024; s += 256) {
        int r = s >> 4, c = (s & 15) * 8;
        cpa16(dpre + r * F2_PS + c, g_d + (size_t)(row0 + r) * NL + c);
    }
    cpa_commit();
    load_B(0, 0);
    load_B(1, 32);
    cpa_wait<1>();
    __syncthreads();
    make_mu(0, 0);

    int lrow = lane & 15;
    int lk8  = (lane >> 4) << 3;
    uint32_t aOff = (uint32_t)((wm * 32 + lrow) * F2_AS + lk8) * 2;
    uint32_t bOff = (uint32_t)(lrow * F2_BS + wn * 32 + lk8) * 2;

    const int NCH = NL / 32;   // 32
    int stW = 2, stM = 1, stC = 0;
    for (int ch = 0; ch < NCH; ch++) {
        if (ch + 2 < NCH) load_B(stW, (ch + 2) * 32);
        if (ch + 1 < NCH) make_mu(stM, ch + 1);
        if (ch + 2 < NCH)      cpa_wait<2>();
        else if (ch + 1 < NCH) cpa_wait<1>();
        else                   cpa_wait<0>();
        __syncthreads();

        uint32_t aSt = sA + stC * F2_A_BYTES + aOff;
        uint32_t bSt = sB + stC * F2_B_BYTES + bOff;
#pragma unroll
        for (int kk = 0; kk < 2; kk++) {
            uint32_t a0[4], a1[4];
            ldsm_x4(aSt + kk * 32,                  a0[0], a0[1], a0[2], a0[3]);
            ldsm_x4(aSt + kk * 32 + 16 * F2_AS * 2, a1[0], a1[1], a1[2], a1[3]);
            uint32_t t0[4], t1[4];
            ldsm_x4_t(bSt + kk * (16 * F2_BS * 2),      t0[0], t0[1], t0[2], t0[3]);
            ldsm_x4_t(bSt + kk * (16 * F2_BS * 2) + 32, t1[0], t1[1], t1[2], t1[3]);
            mma16816(acc[0][0], a0[0], a0[1], a0[2], a0[3], t0[0], t0[1]);
            mma16816(acc[0][1], a0[0], a0[1], a0[2], a0[3], t0[2], t0[3]);
            mma16816(acc[0][2], a0[0], a0[1], a0[2], a0[3], t1[0], t1[1]);
            mma16816(acc[0][3], a0[0], a0[1], a0[2], a0[3], t1[2], t1[3]);
            mma16816(acc[1][0], a1[0], a1[1], a1[2], a1[3], t0[0], t0[1]);
            mma16816(acc[1][1], a1[0], a1[1], a1[2], a1[3], t0[2], t0[3]);
            mma16816(acc[1][2], a1[0], a1[1], a1[2], a1[3], t1[0], t1[1]);
            mma16816(acc[1][3], a1[0], a1[1], a1[2], a1[3], t1[2], t1[3]);
        }
        stW = (stW == 2) ? 0 : stW + 1;
        stM = (stM == 2) ? 0 : stM + 1;
        stC = (stC == 2) ? 0 : stC + 1;
    }

    int erow = lane >> 2;
    int ecol = 2 * (lane & 3);
#pragma unroll
    for (int i = 0; i < 2; i++) {
#pragma unroll
        for (int j = 0; j < 4; j++) {
            int c = wn * 32 + j * 8 + ecol;
            if (c < NC) {
                int r_lo = row0 + wm * 32 + i * 16 + erow;
                *reinterpret_cast<float2*>(out + (size_t)r_lo * NC + c) =
                    make_float2(acc[i][j][0], acc[i][j][1]);
                *reinterpret_cast<float2*>(out + (size_t)(r_lo + 8) * NC + c) =
                    make_float2(acc[i][j][2], acc[i][j][3]);
            }
        }
    }
}

// -------- launch --------
extern "C" void kernel_launch(void* const* d_in, const int* in_sizes, int n_in,
                              void* d_out, int out_size) {
    const float* feat = nullptr;
    const float* mask = nullptr;
    const float* W    = nullptr;
    const float* bias = nullptr;
    const float* pi   = nullptr;
    for (int i = 0; i < n_in; i++) {
        switch (in_sizes[i]) {
            case BB * NF: feat = (const float*)d_in[i]; break;
            case NU * NF: mask = (const float*)d_in[i]; break;
            case NU * NL: W    = (const float*)d_in[i]; break;
            case NL:      bias = (const float*)d_in[i]; break;
            case NL * NC: pi   = (const float*)d_in[i]; break;
            default: break;
        }
    }
    if (!feat && n_in > 0) feat = (const float*)d_in[0];
    if (!mask && n_in > 1) mask = (const float*)d_in[1];
    if (!W    && n_in > 2) W    = (const float*)d_in[2];
    if (!bias && n_in > 3) bias = (const float*)d_in[3];
    if (!pi   && n_in > 4) pi   = (const float*)d_in[4];

    cudaFuncSetAttribute(k_gemm1,  cudaFuncAttributeMaxDynamicSharedMemorySize, G1_SMEM);
    cudaFuncSetAttribute(k_fused2, cudaFuncAttributeMaxDynamicSharedMemorySize, F2_SMEM);

    k_prep<<<640, 256>>>(W, pi, mask);
    k_gather<<<BB / 4, 256>>>(feat);
    k_gemm1<<<dim3(NL / 128, BB / 128), 128, G1_SMEM>>>(bias);
    k_fused2<<<BB / 64, 256, F2_SMEM>>>((float*)d_out);
    (void)out_size;
}

// round 15
// speedup vs baseline: 1.0769x; 1.0769x over previous
#include <cuda_runtime.h>
#include <cuda_bf16.h>
#include <cstdint>
#include <cstddef>

#define BB 16384   // batch
#define NF 512     // features
#define NU 256     // used features
#define NL 1024    // leaves / decision node slots
#define NC 100     // classes
#define NCP 128    // classes padded

// -------- device scratch (static; no allocations anywhere) --------
__device__ int            g_idx[NU];
__device__ __nv_bfloat16  g_xb[(size_t)BB * NU];
__device__ __nv_bfloat16  g_Wb[(size_t)NU * NL];    // W bf16, [k][n]
__device__ __nv_bfloat16  g_probs[(size_t)NL * NCP];
__device__ __nv_bfloat16  g_d[(size_t)BB * NL];
__device__ float          g_part[2][(size_t)BB * NCP];   // split-K partials

// -------- cp.async helpers --------
__device__ __forceinline__ void cpa16(void* smem, const void* gmem) {
    uint32_t s = (uint32_t)__cvta_generic_to_shared(smem);
    asm volatile("cp.async.cg.shared.global [%0], [%1], 16;\n" :: "r"(s), "l"(gmem));
}
__device__ __forceinline__ void cpa_commit() { asm volatile("cp.async.commit_group;\n" ::: "memory"); }
template<int N> __device__ __forceinline__ void cpa_wait() { asm volatile("cp.async.wait_group %0;\n" :: "n"(N) : "memory"); }

// -------- ldmatrix / mma.sync helpers --------
__device__ __forceinline__ void ldsm_x4(uint32_t addr, uint32_t& r0, uint32_t& r1,
                                        uint32_t& r2, uint32_t& r3) {
    asm volatile("ldmatrix.sync.aligned.m8n8.x4.shared.b16 {%0,%1,%2,%3}, [%4];"
                 : "=r"(r0), "=r"(r1), "=r"(r2), "=r"(r3) : "r"(addr));
}
__device__ __forceinline__ void ldsm_x4_t(uint32_t addr, uint32_t& r0, uint32_t& r1,
                                          uint32_t& r2, uint32_t& r3) {
    asm volatile("ldmatrix.sync.aligned.m8n8.x4.trans.shared.b16 {%0,%1,%2,%3}, [%4];"
                 : "=r"(r0), "=r"(r1), "=r"(r2), "=r"(r3) : "r"(addr));
}
__device__ __forceinline__ void mma16816(float* c, uint32_t a0, uint32_t a1, uint32_t a2,
                                         uint32_t a3, uint32_t b0, uint32_t b1) {
    asm volatile("mma.sync.aligned.m16n8k16.row.col.f32.bf16.bf16.f32 "
                 "{%0,%1,%2,%3}, {%4,%5,%6,%7}, {%8,%9}, {%0,%1,%2,%3};"
                 : "+f"(c[0]), "+f"(c[1]), "+f"(c[2]), "+f"(c[3])
                 : "r"(a0), "r"(a1), "r"(a2), "r"(a3), "r"(b0), "r"(b1));
}

// -------- coalesced gather: 4 rows/block via SMEM staging --------
__global__ __launch_bounds__(256) void k_gather(const float* __restrict__ feat) {
    __shared__ float rows[4][NF];
    __shared__ int sidx[NU];
    int t = threadIdx.x;
    sidx[t] = g_idx[t];
    int row0 = blockIdx.x * 4;
    const float4* src = reinterpret_cast<const float4*>(feat + (size_t)row0 * NF);
    float4* dst4 = reinterpret_cast<float4*>(&rows[0][0]);
    dst4[t] = src[t];
    dst4[t + 256] = src[t + 256];
    __syncthreads();
#pragma unroll
    for (int r = 0; r < 4; r++)
        g_xb[(size_t)(row0 + r) * NU + t] = __float2bfloat16(rows[r][sidx[t]]);
}

// -------- merged prep: 0..255 W conv | 256..383 softmax(pi) | 384..639 idx --------
__global__ __launch_bounds__(256) void k_prep(const float* __restrict__ W,
                                              const float* __restrict__ pi,
                                              const float* __restrict__ mask) {
    int b = blockIdx.x;
    if (b < 256) {
        int i = b * 256 + threadIdx.x;
        float4 v = reinterpret_cast<const float4*>(W)[i];
        __nv_bfloat162 p0 = __floats2bfloat162_rn(v.x, v.y);
        __nv_bfloat162 p1 = __floats2bfloat162_rn(v.z, v.w);
        uint2 u;
        u.x = *reinterpret_cast<unsigned*>(&p0);
        u.y = *reinterpret_cast<unsigned*>(&p1);
        reinterpret_cast<uint2*>(g_Wb)[i] = u;
    } else if (b < 384) {
        int w = (b - 256) * 8 + (threadIdx.x >> 5);
        int lane = threadIdx.x & 31;
        const float* row = pi + (size_t)w * NC;
        float4 v;
        if (lane < 25) v = reinterpret_cast<const float4*>(row)[lane];
        else v = make_float4(-1e30f, -1e30f, -1e30f, -1e30f);
        float m = fmaxf(fmaxf(v.x, v.y), fmaxf(v.z, v.w));
#pragma unroll
        for (int o = 16; o > 0; o >>= 1) m = fmaxf(m, __shfl_xor_sync(0xffffffffu, m, o));
        float e0 = (lane < 25) ? expf(v.x - m) : 0.f;
        float e1 = (lane < 25) ? expf(v.y - m) : 0.f;
        float e2 = (lane < 25) ? expf(v.z - m) : 0.f;
        float e3 = (lane < 25) ? expf(v.w - m) : 0.f;
        float s = e0 + e1 + e2 + e3;
#pragma unroll
        for (int o = 16; o > 0; o >>= 1) s += __shfl_xor_sync(0xffffffffu, s, o);
        float inv = 1.f / s;
        __nv_bfloat162 p0 = __floats2bfloat162_rn(e0 * inv, e1 * inv);
        __nv_bfloat162 p1 = __floats2bfloat162_rn(e2 * inv, e3 * inv);
        uint2 u;
        u.x = *reinterpret_cast<unsigned*>(&p0);
        u.y = *reinterpret_cast<unsigned*>(&p1);
        reinterpret_cast<uint2*>(g_probs + (size_t)w * NCP)[lane] = u;
    } else {
        int j = b - 384;
        int t = threadIdx.x;
        if (t < 128) {
            float4 v = reinterpret_cast<const float4*>(mask + (size_t)j * NF)[t];
            int f = -1;
            if      (v.x > 0.5f) f = 4 * t;
            else if (v.y > 0.5f) f = 4 * t + 1;
            else if (v.z > 0.5f) f = 4 * t + 2;
            else if (v.w > 0.5f) f = 4 * t + 3;
            if (f >= 0) g_idx[j] = f;
        }
    }
}

// -------- GEMM1 (round-11 proven): d = sigmoid(xb @ Wb + b)  [16384x1024x256]
// 256 threads, 128x128 tile, warp tile 32x64 (4m x 2n), BK=64, 3-stage cp.async.
#define G1_AS 72
#define G1_BS 136
#define G1_A_BYTES (128 * G1_AS * 2)   // 18432 per stage
#define G1_B_BYTES (64 * G1_BS * 2)    // 17408 per stage
#define G1_SMEM (3 * (G1_A_BYTES + G1_B_BYTES))   // 107520
__global__ __launch_bounds__(256, 2) void k_gemm1(const float* __restrict__ bias) {
    extern __shared__ __align__(16) unsigned char smem[];
    __nv_bfloat16* As = reinterpret_cast<__nv_bfloat16*>(smem);                  // 3 x 128x72
    __nv_bfloat16* Bs = reinterpret_cast<__nv_bfloat16*>(smem + 3 * G1_A_BYTES); // 3 x 64x136
    uint32_t sbase = (uint32_t)__cvta_generic_to_shared(smem);
    uint32_t sA = sbase;
    uint32_t sB = sbase + 3 * G1_A_BYTES;

    int tid = threadIdx.x, wid = tid >> 5, lane = tid & 31;
    int wm = wid & 3, wn = wid >> 2;           // 4(m) x 2(n), warp tile 32x64
    int n0 = blockIdx.x * 128, row0 = blockIdx.y * 128;

    float acc[2][8][4];
#pragma unroll
    for (int i = 0; i < 2; i++)
#pragma unroll
        for (int j = 0; j < 8; j++)
#pragma unroll
            for (int q = 0; q < 4; q++) acc[i][j][q] = 0.f;

    auto load_stage = [&](int st, int ko) {
        __nv_bfloat16* a = As + st * 128 * G1_AS;
        __nv_bfloat16* b = Bs + st * 64 * G1_BS;
#pragma unroll
        for (int s = tid; s < 1024; s += 256) {
            int r = s >> 3, c = (s & 7) * 8;
            cpa16(a + r * G1_AS + c, g_xb + (size_t)(row0 + r) * NU + ko + c);
        }
#pragma unroll
        for (int s = tid; s < 1024; s += 256) {
            int r = s >> 4, c = (s & 15) * 8;
            cpa16(b + r * G1_BS + c, g_Wb + (size_t)(ko + r) * NL + n0 + c);
        }
        cpa_commit();
    };

    int lrow = lane & 15;
    int lk8  = (lane >> 4) << 3;
    uint32_t aOff = (uint32_t)((wm * 32 + lrow) * G1_AS + lk8) * 2;
    uint32_t bOff = (uint32_t)(lrow * G1_BS + wn * 64 + lk8) * 2;

    load_stage(0, 0);
    load_stage(1, 64);
    cpa_wait<1>();
    __syncthreads();

    const int NCH = NU / 64;   // 4
    for (int ch = 0; ch < NCH; ch++) {
        if (ch + 2 < NCH) load_stage((ch + 2) % 3, (ch + 2) * 64);

        uint32_t aSt = sA + (ch % 3) * G1_A_BYTES + aOff;
        uint32_t bSt = sB + (ch % 3) * G1_B_BYTES + bOff;
#pragma unroll
        for (int kk = 0; kk < 4; kk++) {
            uint32_t a0[4], a1[4];
            ldsm_x4(aSt + kk * 32,                  a0[0], a0[1], a0[2], a0[3]);
            ldsm_x4(aSt + kk * 32 + 16 * G1_AS * 2, a1[0], a1[1], a1[2], a1[3]);
#pragma unroll
            for (int jj = 0; jj < 4; jj++) {
                uint32_t t[4];
                ldsm_x4_t(bSt + kk * (16 * G1_BS * 2) + jj * 32, t[0], t[1], t[2], t[3]);
                mma16816(acc[0][2 * jj],     a0[0], a0[1], a0[2], a0[3], t[0], t[1]);
                mma16816(acc[0][2 * jj + 1], a0[0], a0[1], a0[2], a0[3], t[2], t[3]);
                mma16816(acc[1][2 * jj],     a1[0], a1[1], a1[2], a1[3], t[0], t[1]);
                mma16816(acc[1][2 * jj + 1], a1[0], a1[1], a1[2], a1[3], t[2], t[3]);
            }
        }
        if (ch + 1 < NCH) {
            if (ch + 2 < NCH) cpa_wait<1>();
            else              cpa_wait<0>();
            __syncthreads();
        }
    }

    int erow = lane >> 2;
    int ecol = 2 * (lane & 3);
#pragma unroll
    for (int i = 0; i < 2; i++) {
#pragma unroll
        for (int j = 0; j < 8; j++) {
            int cbase = n0 + wn * 64 + j * 8 + ecol;
            float b0 = bias[cbase], b1 = bias[cbase + 1];
            int r_lo = row0 + wm * 32 + i * 16 + erow;
            float z0 = acc[i][j][0] + b0, z1 = acc[i][j][1] + b1;
            __nv_bfloat162 p0 = __floats2bfloat162_rn(1.f / (1.f + __expf(-z0)),
                                                      1.f / (1.f + __expf(-z1)));
            *reinterpret_cast<__nv_bfloat162*>(g_d + (size_t)r_lo * NL + cbase) = p0;
            float z2 = acc[i][j][2] + b0, z3 = acc[i][j][3] + b1;
            __nv_bfloat162 p1 = __floats2bfloat162_rn(1.f / (1.f + __expf(-z2)),
                                                      1.f / (1.f + __expf(-z3)));
            *reinterpret_cast<__nv_bfloat162*>(g_d + (size_t)(r_lo + 8) * NL + cbase) = p1;
        }
    }
}

// -------- fused tree-product + GEMM2, SPLIT-K: part[h] = mu(d)[:,hK] @ probs[hK,:]
// blockIdx.y = K-half (leaves [h*512,(h+1)*512), 16 chunks of 32).
// Otherwise identical to the proven round-11 structure.
#define F2_PS 136
#define F2_P_BYTES (64 * F2_PS * 2)      // 17408
#define F2_BS 136
#define F2_B_BYTES (32 * F2_BS * 2)      // 8704 per stage
#define F2_AS 40
#define F2_A_BYTES (64 * F2_AS * 2)      // 5120 per stage
#define F2_SMEM (F2_P_BYTES + 3 * F2_B_BYTES + 3 * F2_A_BYTES)   // 58880
__global__ __launch_bounds__(256, 3) void k_fused2() {
    extern __shared__ __align__(16) unsigned char smem[];
    __nv_bfloat16* dpre = reinterpret_cast<__nv_bfloat16*>(smem);
    __nv_bfloat16* Bs   = reinterpret_cast<__nv_bfloat16*>(smem + F2_P_BYTES);
    __nv_bfloat16* As   = reinterpret_cast<__nv_bfloat16*>(smem + F2_P_BYTES + 3 * F2_B_BYTES);
    uint32_t sbase = (uint32_t)__cvta_generic_to_shared(smem);
    uint32_t sB = sbase + F2_P_BYTES;
    uint32_t sA = sB + 3 * F2_B_BYTES;

    int tid = threadIdx.x, wid = tid >> 5, lane = tid & 31;
    int wm = wid & 1, wn = wid >> 1;
    int row0 = blockIdx.x * 64;
    int half = blockIdx.y;               // 0 or 1
    int base = half * 16;                // first chunk index

    int mrow = tid >> 2, mgrp = tid & 3;
    const __nv_bfloat16* prow = dpre + mrow * F2_PS;
    const __nv_bfloat16* grow = g_d + (size_t)(row0 + mrow) * NL;

    float acc[2][4][4];
#pragma unroll
    for (int i = 0; i < 2; i++)
#pragma unroll
        for (int j = 0; j < 4; j++)
#pragma unroll
            for (int q = 0; q < 4; q++) acc[i][j][q] = 0.f;

    auto load_B = [&](int st, int ko) {
        __nv_bfloat16* b = Bs + st * 32 * F2_BS;
#pragma unroll
        for (int s = tid; s < 512; s += 256) {
            int r = s >> 4, c = (s & 15) * 8;
            cpa16(b + r * F2_BS + c, g_probs + (size_t)(ko + r) * NCP + c);
        }
        cpa_commit();
    };

    auto make_mu = [&](int st, int ch) {
        int h = ch * 4 + mgrp;
        float P = 1.f;
#pragma unroll
        for (int lev = 0; lev < 7; lev++) {
            int node = (1 << lev) + (h >> (7 - lev));
            int bit  = (h >> (6 - lev)) & 1;
            float dv = __bfloat162float(prow[node]);
            P *= bit ? (1.f - dv) : dv;
        }
        float d7 = __bfloat162float(grow[128 + h]);
        __nv_bfloat162 p8 = *reinterpret_cast<const __nv_bfloat162*>(grow + 256 + 2 * h);
        float d8a = __bfloat162float(__low2bfloat16(p8));
        float d8b = __bfloat162float(__high2bfloat16(p8));
        uint2 q9 = *reinterpret_cast<const uint2*>(grow + 512 + 4 * h);
        __nv_bfloat162 q9a = *reinterpret_cast<__nv_bfloat162*>(&q9.x);
        __nv_bfloat162 q9b = *reinterpret_cast<__nv_bfloat162*>(&q9.y);
        float d90 = __bfloat162float(__low2bfloat16(q9a));
        float d91 = __bfloat162float(__high2bfloat16(q9a));
        float d92 = __bfloat162float(__low2bfloat16(q9b));
        float d93 = __bfloat162float(__high2bfloat16(q9b));
        float pa = P * d7;
        float pb = P * (1.f - d7);
        float m0 = pa * d8a * d90;
        float m1 = pa * d8a * (1.f - d90);
        float m2 = pa * (1.f - d8a) * d91;
        float m3 = pa * (1.f - d8a) * (1.f - d91);
        float m4 = pb * d8b * d92;
        float m5 = pb * d8b * (1.f - d92);
        float m6 = pb * (1.f - d8b) * d93;
        float m7 = pb * (1.f - d8b) * (1.f - d93);
        __nv_bfloat162 o0 = __floats2bfloat162_rn(m0, m1);
        __nv_bfloat162 o1 = __floats2bfloat162_rn(m2, m3);
        __nv_bfloat162 o2 = __floats2bfloat162_rn(m4, m5);
        __nv_bfloat162 o3 = __floats2bfloat162_rn(m6, m7);
        uint4 u;
        u.x = *reinterpret_cast<unsigned*>(&o0);
        u.y = *reinterpret_cast<unsigned*>(&o1);
        u.z = *reinterpret_cast<unsigned*>(&o2);
        u.w = *reinterpret_cast<unsigned*>(&o3);
        *reinterpret_cast<uint4*>(As + st * 64 * F2_AS + mrow * F2_AS + mgrp * 8) = u;
    };

#pragma unroll
    for (int s = tid; s < 1024; s += 256) {
        int r = s >> 4, c = (s & 15) * 8;
        cpa16(dpre + r * F2_PS + c, g_d + (size_t)(row0 + r) * NL + c);
    }
    cpa_commit();
    load_B(0, (base + 0) * 32);
    load_B(1, (base + 1) * 32);
    cpa_wait<1>();
    __syncthreads();
    make_mu(0, base + 0);

    int lrow = lane & 15;
    int lk8  = (lane >> 4) << 3;
    uint32_t aOff = (uint32_t)((wm * 32 + lrow) * F2_AS + lk8) * 2;
    uint32_t bOff = (uint32_t)(lrow * F2_BS + wn * 32 + lk8) * 2;

    const int NCH = 16;                 // chunks per half
    int stW = 2, stM = 1, stC = 0;
    for (int i2 = 0; i2 < NCH; i2++) {
        if (i2 + 2 < NCH) load_B(stW, (base + i2 + 2) * 32);
        if (i2 + 1 < NCH) make_mu(stM, base + i2 + 1);
        if (i2 + 2 < NCH)      cpa_wait<2>();
        else if (i2 + 1 < NCH) cpa_wait<1>();
        else                   cpa_wait<0>();
        __syncthreads();

        uint32_t aSt = sA + stC * F2_A_BYTES + aOff;
        uint32_t bSt = sB + stC * F2_B_BYTES + bOff;
#pragma unroll
        for (int kk = 0; kk < 2; kk++) {
            uint32_t a0[4], a1[4];
            ldsm_x4(aSt + kk * 32,                  a0[0], a0[1], a0[2], a0[3]);
            ldsm_x4(aSt + kk * 32 + 16 * F2_AS * 2, a1[0], a1[1], a1[2], a1[3]);
            uint32_t t0[4], t1[4];
            ldsm_x4_t(bSt + kk * (16 * F2_BS * 2),      t0[0], t0[1], t0[2], t0[3]);
            ldsm_x4_t(bSt + kk * (16 * F2_BS * 2) + 32, t1[0], t1[1], t1[2], t1[3]);
            mma16816(acc[0][0], a0[0], a0[1], a0[2], a0[3], t0[0], t0[1]);
            mma16816(acc[0][1], a0[0], a0[1], a0[2], a0[3], t0[2], t0[3]);
            mma16816(acc[0][2], a0[0], a0[1], a0[2], a0[3], t1[0], t1[1]);
            mma16816(acc[0][3], a0[0], a0[1], a0[2], a0[3], t1[2], t1[3]);
            mma16816(acc[1][0], a1[0], a1[1], a1[2], a1[3], t0[0], t0[1]);
            mma16816(acc[1][1], a1[0], a1[1], a1[2], a1[3], t0[2], t0[3]);
            mma16816(acc[1][2], a1[0], a1[1], a1[2], a1[3], t1[0], t1[1]);
            mma16816(acc[1][3], a1[0], a1[1], a1[2], a1[3], t1[2], t1[3]);
        }
        stW = (stW == 2) ? 0 : stW + 1;
        stM = (stM == 2) ? 0 : stM + 1;
        stC = (stC == 2) ? 0 : stC + 1;
    }

    // epilogue: fragments -> g_part[half] (f32, stride NCP, all 128 cols)
    float* pout = &g_part[half][0];
    int erow = lane >> 2;
    int ecol = 2 * (lane & 3);
#pragma unroll
    for (int i = 0; i < 2; i++) {
#pragma unroll
        for (int j = 0; j < 4; j++) {
            int c = wn * 32 + j * 8 + ecol;
            int r_lo = row0 + wm * 32 + i * 16 + erow;
            *reinterpret_cast<float2*>(pout + (size_t)r_lo * NCP + c) =
                make_float2(acc[i][j][0], acc[i][j][1]);
            *reinterpret_cast<float2*>(pout + (size_t)(r_lo + 8) * NCP + c) =
                make_float2(acc[i][j][2], acc[i][j][3]);
        }
    }
}

// -------- reduce: out = part0 + part1, cols < 100 --------
__global__ __launch_bounds__(256) void k_red(float* __restrict__ out) {
    int idx = blockIdx.x * 256 + threadIdx.x;     // 16384 * 25 float4 groups
    int r = idx / 25, g = idx % 25;
    int c = g * 4;
    float4 a = *reinterpret_cast<const float4*>(&g_part[0][(size_t)r * NCP + c]);
    float4 b = *reinterpret_cast<const float4*>(&g_part[1][(size_t)r * NCP + c]);
    float4 o = make_float4(a.x + b.x, a.y + b.y, a.z + b.z, a.w + b.w);
    *reinterpret_cast<float4*>(out + (size_t)r * NC + c) = o;
}

// -------- launch --------
extern "C" void kernel_launch(void* const* d_in, const int* in_sizes, int n_in,
                              void* d_out, int out_size) {
    const float* feat = nullptr;
    const float* mask = nullptr;
    const float* W    = nullptr;
    const float* bias = nullptr;
    const float* pi   = nullptr;
    for (int i = 0; i < n_in; i++) {
        switch (in_sizes[i]) {
            case BB * NF: feat = (const float*)d_in[i]; break;
            case NU * NF: mask = (const float*)d_in[i]; break;
            case NU * NL: W    = (const float*)d_in[i]; break;
            case NL:      bias = (const float*)d_in[i]; break;
            case NL * NC: pi   = (const float*)d_in[i]; break;
            default: break;
        }
    }
    if (!feat && n_in > 0) feat = (const float*)d_in[0];
    if (!mask && n_in > 1) mask = (const float*)d_in[1];
    if (!W    && n_in > 2) W    = (const float*)d_in[2];
    if (!bias && n_in > 3) bias = (const float*)d_in[3];
    if (!pi   && n_in > 4) pi   = (const float*)d_in[4];

    cudaFuncSetAttribute(k_gemm1,  cudaFuncAttributeMaxDynamicSharedMemorySize, G1_SMEM);
    cudaFuncSetAttribute(k_fused2, cudaFuncAttributeMaxDynamicSharedMemorySize, F2_SMEM);

    k_prep<<<640, 256>>>(W, pi, mask);
    k_gather<<<BB / 4, 256>>>(feat);
    k_gemm1<<<dim3(NL / 128, BB / 128), 256, G1_SMEM>>>(bias);
    k_fused2<<<dim3(BB / 64, 2), 256, F2_SMEM>>>();
    k_red<<<BB * 25 / 256, 256>>>((float*)d_out);
    (void)out_size;
}

// round 16
// speedup vs baseline: 1.2532x; 1.1637x over previous
#include <cuda_runtime.h>
#include <cuda_bf16.h>
#include <cstdint>
#include <cstddef>

#define BB 16384   // batch
#define NF 512     // features
#define NU 256     // used features
#define NL 1024    // leaves / decision node slots
#define NC 100     // classes
#define NCP 128    // classes padded

// -------- device scratch (static; no allocations anywhere) --------
__device__ int            g_idx[NU];
__device__ __nv_bfloat16  g_xb[(size_t)BB * NU];
__device__ __nv_bfloat16  g_Wb[(size_t)NU * NL];    // W bf16, [k][n]
__device__ __nv_bfloat16  g_probs[(size_t)NL * NCP];
__device__ __nv_bfloat16  g_d[(size_t)BB * NL];

// -------- cp.async helpers --------
__device__ __forceinline__ void cpa16(void* smem, const void* gmem) {
    uint32_t s = (uint32_t)__cvta_generic_to_shared(smem);
    asm volatile("cp.async.cg.shared.global [%0], [%1], 16;\n" :: "r"(s), "l"(gmem));
}
__device__ __forceinline__ void cpa_commit() { asm volatile("cp.async.commit_group;\n" ::: "memory"); }
template<int N> __device__ __forceinline__ void cpa_wait() { asm volatile("cp.async.wait_group %0;\n" :: "n"(N) : "memory"); }

// -------- ldmatrix / mma.sync helpers --------
__device__ __forceinline__ void ldsm_x4(uint32_t addr, uint32_t& r0, uint32_t& r1,
                                        uint32_t& r2, uint32_t& r3) {
    asm volatile("ldmatrix.sync.aligned.m8n8.x4.shared.b16 {%0,%1,%2,%3}, [%4];"
                 : "=r"(r0), "=r"(r1), "=r"(r2), "=r"(r3) : "r"(addr));
}
__device__ __forceinline__ void ldsm_x4_t(uint32_t addr, uint32_t& r0, uint32_t& r1,
                                          uint32_t& r2, uint32_t& r3) {
    asm volatile("ldmatrix.sync.aligned.m8n8.x4.trans.shared.b16 {%0,%1,%2,%3}, [%4];"
                 : "=r"(r0), "=r"(r1), "=r"(r2), "=r"(r3) : "r"(addr));
}
__device__ __forceinline__ void mma16816(float* c, uint32_t a0, uint32_t a1, uint32_t a2,
                                         uint32_t a3, uint32_t b0, uint32_t b1) {
    asm volatile("mma.sync.aligned.m16n8k16.row.col.f32.bf16.bf16.f32 "
                 "{%0,%1,%2,%3}, {%4,%5,%6,%7}, {%8,%9}, {%0,%1,%2,%3};"
                 : "+f"(c[0]), "+f"(c[1]), "+f"(c[2]), "+f"(c[3])
                 : "r"(a0), "r"(a1), "r"(a2), "r"(a3), "r"(b0), "r"(b1));
}

// -------- coalesced gather: 4 rows/block via SMEM staging --------
__global__ __launch_bounds__(256) void k_gather(const float* __restrict__ feat) {
    __shared__ float rows[4][NF];
    __shared__ int sidx[NU];
    int t = threadIdx.x;
    sidx[t] = g_idx[t];
    int row0 = blockIdx.x * 4;
    const float4* src = reinterpret_cast<const float4*>(feat + (size_t)row0 * NF);
    float4* dst4 = reinterpret_cast<float4*>(&rows[0][0]);
    dst4[t] = src[t];
    dst4[t + 256] = src[t + 256];
    __syncthreads();
#pragma unroll
    for (int r = 0; r < 4; r++)
        g_xb[(size_t)(row0 + r) * NU + t] = __float2bfloat16(rows[r][sidx[t]]);
}

// -------- merged prep: 0..255 W conv | 256..383 softmax(pi) | 384..639 idx --------
__global__ __launch_bounds__(256) void k_prep(const float* __restrict__ W,
                                              const float* __restrict__ pi,
                                              const float* __restrict__ mask) {
    int b = blockIdx.x;
    if (b < 256) {
        int i = b * 256 + threadIdx.x;
        float4 v = reinterpret_cast<const float4*>(W)[i];
        __nv_bfloat162 p0 = __floats2bfloat162_rn(v.x, v.y);
        __nv_bfloat162 p1 = __floats2bfloat162_rn(v.z, v.w);
        uint2 u;
        u.x = *reinterpret_cast<unsigned*>(&p0);
        u.y = *reinterpret_cast<unsigned*>(&p1);
        reinterpret_cast<uint2*>(g_Wb)[i] = u;
    } else if (b < 384) {
        int w = (b - 256) * 8 + (threadIdx.x >> 5);
        int lane = threadIdx.x & 31;
        const float* row = pi + (size_t)w * NC;
        float4 v;
        if (lane < 25) v = reinterpret_cast<const float4*>(row)[lane];
        else v = make_float4(-1e30f, -1e30f, -1e30f, -1e30f);
        float m = fmaxf(fmaxf(v.x, v.y), fmaxf(v.z, v.w));
#pragma unroll
        for (int o = 16; o > 0; o >>= 1) m = fmaxf(m, __shfl_xor_sync(0xffffffffu, m, o));
        float e0 = (lane < 25) ? expf(v.x - m) : 0.f;
        float e1 = (lane < 25) ? expf(v.y - m) : 0.f;
        float e2 = (lane < 25) ? expf(v.z - m) : 0.f;
        float e3 = (lane < 25) ? expf(v.w - m) : 0.f;
        float s = e0 + e1 + e2 + e3;
#pragma unroll
        for (int o = 16; o > 0; o >>= 1) s += __shfl_xor_sync(0xffffffffu, s, o);
        float inv = 1.f / s;
        __nv_bfloat162 p0 = __floats2bfloat162_rn(e0 * inv, e1 * inv);
        __nv_bfloat162 p1 = __floats2bfloat162_rn(e2 * inv, e3 * inv);
        uint2 u;
        u.x = *reinterpret_cast<unsigned*>(&p0);
        u.y = *reinterpret_cast<unsigned*>(&p1);
        reinterpret_cast<uint2*>(g_probs + (size_t)w * NCP)[lane] = u;
    } else {
        int j = b - 384;
        int t = threadIdx.x;
        if (t < 128) {
            float4 v = reinterpret_cast<const float4*>(mask + (size_t)j * NF)[t];
            int f = -1;
            if      (v.x > 0.5f) f = 4 * t;
            else if (v.y > 0.5f) f = 4 * t + 1;
            else if (v.z > 0.5f) f = 4 * t + 2;
            else if (v.w > 0.5f) f = 4 * t + 3;
            if (f >= 0) g_idx[j] = f;
        }
    }
}

// -------- GEMM1: d = sigmoid(xb @ Wb + b)  [16384x1024x256]
// 64x128 block, 32x32 warp tile (2m x 4n), BK=64, 2-stage, 4 CTAs/SM target.
#define G1_AS 72
#define G1_BS 136
#define G1_A_BYTES (64 * G1_AS * 2)    // 9216 per stage
#define G1_B_BYTES (64 * G1_BS * 2)    // 17408 per stage
#define G1_SMEM (2 * (G1_A_BYTES + G1_B_BYTES))   // 53248
__global__ __launch_bounds__(256, 4) void k_gemm1(const float* __restrict__ bias) {
    extern __shared__ __align__(16) unsigned char smem[];
    __nv_bfloat16* As = reinterpret_cast<__nv_bfloat16*>(smem);                  // 2 x 64x72
    __nv_bfloat16* Bs = reinterpret_cast<__nv_bfloat16*>(smem + 2 * G1_A_BYTES); // 2 x 64x136
    uint32_t sbase = (uint32_t)__cvta_generic_to_shared(smem);
    uint32_t sA = sbase;
    uint32_t sB = sbase + 2 * G1_A_BYTES;

    int tid = threadIdx.x, wid = tid >> 5, lane = tid & 31;
    int wm = wid & 1, wn = wid >> 1;           // 2(m) x 4(n), warp tile 32x32
    int n0 = blockIdx.x * 128, row0 = blockIdx.y * 64;

    float acc[2][4][4];
#pragma unroll
    for (int i = 0; i < 2; i++)
#pragma unroll
        for (int j = 0; j < 4; j++)
#pragma unroll
            for (int q = 0; q < 4; q++) acc[i][j][q] = 0.f;

    auto load_stage = [&](int st, int ko) {
        __nv_bfloat16* a = As + st * 64 * G1_AS;
        __nv_bfloat16* b = Bs + st * 64 * G1_BS;
#pragma unroll
        for (int s = tid; s < 512; s += 256) {          // A: 64 x 64 (2/thread)
            int r = s >> 3, c = (s & 7) * 8;
            cpa16(a + r * G1_AS + c, g_xb + (size_t)(row0 + r) * NU + ko + c);
        }
#pragma unroll
        for (int s = tid; s < 1024; s += 256) {         // B: 64 x 128 (4/thread)
            int r = s >> 4, c = (s & 15) * 8;
            cpa16(b + r * G1_BS + c, g_Wb + (size_t)(ko + r) * NL + n0 + c);
        }
        cpa_commit();
    };

    int lrow = lane & 15;
    int lk8  = (lane >> 4) << 3;
    uint32_t aOff = (uint32_t)((wm * 32 + lrow) * G1_AS + lk8) * 2;
    uint32_t bOff = (uint32_t)(lrow * G1_BS + wn * 32 + lk8) * 2;

    load_stage(0, 0);
    const int NCH = NU / 64;   // 4
    for (int ch = 0; ch < NCH; ch++) {
        if (ch + 1 < NCH) { load_stage((ch + 1) & 1, (ch + 1) * 64); cpa_wait<1>(); }
        else              { cpa_wait<0>(); }
        __syncthreads();
        uint32_t aSt = sA + (ch & 1) * G1_A_BYTES + aOff;
        uint32_t bSt = sB + (ch & 1) * G1_B_BYTES + bOff;
#pragma unroll
        for (int kk = 0; kk < 4; kk++) {
            uint32_t a0[4], a1[4];
            ldsm_x4(aSt + kk * 32,                  a0[0], a0[1], a0[2], a0[3]);
            ldsm_x4(aSt + kk * 32 + 16 * G1_AS * 2, a1[0], a1[1], a1[2], a1[3]);
            uint32_t t0[4], t1[4];
            ldsm_x4_t(bSt + kk * (16 * G1_BS * 2),      t0[0], t0[1], t0[2], t0[3]);
            ldsm_x4_t(bSt + kk * (16 * G1_BS * 2) + 32, t1[0], t1[1], t1[2], t1[3]);
            mma16816(acc[0][0], a0[0], a0[1], a0[2], a0[3], t0[0], t0[1]);
            mma16816(acc[0][1], a0[0], a0[1], a0[2], a0[3], t0[2], t0[3]);
            mma16816(acc[0][2], a0[0], a0[1], a0[2], a0[3], t1[0], t1[1]);
            mma16816(acc[0][3], a0[0], a0[1], a0[2], a0[3], t1[2], t1[3]);
            mma16816(acc[1][0], a1[0], a1[1], a1[2], a1[3], t0[0], t0[1]);
            mma16816(acc[1][1], a1[0], a1[1], a1[2], a1[3], t0[2], t0[3]);
            mma16816(acc[1][2], a1[0], a1[1], a1[2], a1[3], t1[0], t1[1]);
            mma16816(acc[1][3], a1[0], a1[1], a1[2], a1[3], t1[2], t1[3]);
        }
        __syncthreads();
    }

    // direct epilogue: bias + sigmoid from fragments -> g_d bf16x2 stores
    int erow = lane >> 2;
    int ecol = 2 * (lane & 3);
#pragma unroll
    for (int i = 0; i < 2; i++) {
#pragma unroll
        for (int j = 0; j < 4; j++) {
            int cbase = n0 + wn * 32 + j * 8 + ecol;
            float b0 = bias[cbase], b1 = bias[cbase + 1];
            int r_lo = row0 + wm * 32 + i * 16 + erow;
            float z0 = acc[i][j][0] + b0, z1 = acc[i][j][1] + b1;
            __nv_bfloat162 p0 = __floats2bfloat162_rn(1.f / (1.f + __expf(-z0)),
                                                      1.f / (1.f + __expf(-z1)));
            *reinterpret_cast<__nv_bfloat162*>(g_d + (size_t)r_lo * NL + cbase) = p0;
            float z2 = acc[i][j][2] + b0, z3 = acc[i][j][3] + b1;
            __nv_bfloat162 p1 = __floats2bfloat162_rn(1.f / (1.f + __expf(-z2)),
                                                      1.f / (1.f + __expf(-z3)));
            *reinterpret_cast<__nv_bfloat162*>(g_d + (size_t)(r_lo + 8) * NL + cbase) = p1;
        }
    }
}

// -------- fused tree-product + GEMM2 (round-11 exact, measured 38.5us) --------
#define F2_PS 136
#define F2_P_BYTES (64 * F2_PS * 2)      // 17408
#define F2_BS 136
#define F2_B_BYTES (32 * F2_BS * 2)      // 8704 per stage
#define F2_AS 40
#define F2_A_BYTES (64 * F2_AS * 2)      // 5120 per stage
#define F2_SMEM (F2_P_BYTES + 3 * F2_B_BYTES + 3 * F2_A_BYTES)   // 58880
__global__ __launch_bounds__(256, 3) void k_fused2(float* __restrict__ out) {
    extern __shared__ __align__(16) unsigned char smem[];
    __nv_bfloat16* dpre = reinterpret_cast<__nv_bfloat16*>(smem);
    __nv_bfloat16* Bs   = reinterpret_cast<__nv_bfloat16*>(smem + F2_P_BYTES);
    __nv_bfloat16* As   = reinterpret_cast<__nv_bfloat16*>(smem + F2_P_BYTES + 3 * F2_B_BYTES);
    uint32_t sbase = (uint32_t)__cvta_generic_to_shared(smem);
    uint32_t sB = sbase + F2_P_BYTES;
    uint32_t sA = sB + 3 * F2_B_BYTES;

    int tid = threadIdx.x, wid = tid >> 5, lane = tid & 31;
    int wm = wid & 1, wn = wid >> 1;
    int row0 = blockIdx.x * 64;

    int mrow = tid >> 2, mgrp = tid & 3;
    const __nv_bfloat16* prow = dpre + mrow * F2_PS;
    const __nv_bfloat16* grow = g_d + (size_t)(row0 + mrow) * NL;

    float acc[2][4][4];
#pragma unroll
    for (int i = 0; i < 2; i++)
#pragma unroll
        for (int j = 0; j < 4; j++)
#pragma unroll
            for (int q = 0; q < 4; q++) acc[i][j][q] = 0.f;

    auto load_B = [&](int st, int ko) {
        __nv_bfloat16* b = Bs + st * 32 * F2_BS;
#pragma unroll
        for (int s = tid; s < 512; s += 256) {
            int r = s >> 4, c = (s & 15) * 8;
            cpa16(b + r * F2_BS + c, g_probs + (size_t)(ko + r) * NCP + c);
        }
        cpa_commit();
    };

    auto make_mu = [&](int st, int ch) {
        int h = ch * 4 + mgrp;
        float P = 1.f;
#pragma unroll
        for (int lev = 0; lev < 7; lev++) {
            int node = (1 << lev) + (h >> (7 - lev));
            int bit  = (h >> (6 - lev)) & 1;
            float dv = __bfloat162float(prow[node]);
            P *= bit ? (1.f - dv) : dv;
        }
        float d7 = __bfloat162float(grow[128 + h]);
        __nv_bfloat162 p8 = *reinterpret_cast<const __nv_bfloat162*>(grow + 256 + 2 * h);
        float d8a = __bfloat162float(__low2bfloat16(p8));
        float d8b = __bfloat162float(__high2bfloat16(p8));
        uint2 q9 = *reinterpret_cast<const uint2*>(grow + 512 + 4 * h);
        __nv_bfloat162 q9a = *reinterpret_cast<__nv_bfloat162*>(&q9.x);
        __nv_bfloat162 q9b = *reinterpret_cast<__nv_bfloat162*>(&q9.y);
        float d90 = __bfloat162float(__low2bfloat16(q9a));
        float d91 = __bfloat162float(__high2bfloat16(q9a));
        float d92 = __bfloat162float(__low2bfloat16(q9b));
        float d93 = __bfloat162float(__high2bfloat16(q9b));
        float pa = P * d7;
        float pb = P * (1.f - d7);
        float m0 = pa * d8a * d90;
        float m1 = pa * d8a * (1.f - d90);
        float m2 = pa * (1.f - d8a) * d91;
        float m3 = pa * (1.f - d8a) * (1.f - d91);
        float m4 = pb * d8b * d92;
        float m5 = pb * d8b * (1.f - d92);
        float m6 = pb * (1.f - d8b) * d93;
        float m7 = pb * (1.f - d8b) * (1.f - d93);
        __nv_bfloat162 o0 = __floats2bfloat162_rn(m0, m1);
        __nv_bfloat162 o1 = __floats2bfloat162_rn(m2, m3);
        __nv_bfloat162 o2 = __floats2bfloat162_rn(m4, m5);
        __nv_bfloat162 o3 = __floats2bfloat162_rn(m6, m7);
        uint4 u;
        u.x = *reinterpret_cast<unsigned*>(&o0);
        u.y = *reinterpret_cast<unsigned*>(&o1);
        u.z = *reinterpret_cast<unsigned*>(&o2);
        u.w = *reinterpret_cast<unsigned*>(&o3);
        *reinterpret_cast<uint4*>(As + st * 64 * F2_AS + mrow * F2_AS + mgrp * 8) = u;
    };

#pragma unroll
    for (int s = tid; s < 1024; s += 256) {
        int r = s >> 4, c = (s & 15) * 8;
        cpa16(dpre + r * F2_PS + c, g_d + (size_t)(row0 + r) * NL + c);
    }
    cpa_commit();
    load_B(0, 0);
    load_B(1, 32);
    cpa_wait<1>();
    __syncthreads();
    make_mu(0, 0);

    int lrow = lane & 15;
    int lk8  = (lane >> 4) << 3;
    uint32_t aOff = (uint32_t)((wm * 32 + lrow) * F2_AS + lk8) * 2;
    uint32_t bOff = (uint32_t)(lrow * F2_BS + wn * 32 + lk8) * 2;

    const int NCH = NL / 32;   // 32
    int stW = 2, stM = 1, stC = 0;
    for (int ch = 0; ch < NCH; ch++) {
        if (ch + 2 < NCH) load_B(stW, (ch + 2) * 32);
        if (ch + 1 < NCH) make_mu(stM, ch + 1);
        if (ch + 2 < NCH)      cpa_wait<2>();
        else if (ch + 1 < NCH) cpa_wait<1>();
        else                   cpa_wait<0>();
        __syncthreads();

        uint32_t aSt = sA + stC * F2_A_BYTES + aOff;
        uint32_t bSt = sB + stC * F2_B_BYTES + bOff;
#pragma unroll
        for (int kk = 0; kk < 2; kk++) {
            uint32_t a0[4], a1[4];
            ldsm_x4(aSt + kk * 32,                  a0[0], a0[1], a0[2], a0[3]);
            ldsm_x4(aSt + kk * 32 + 16 * F2_AS * 2, a1[0], a1[1], a1[2], a1[3]);
            uint32_t t0[4], t1[4];
            ldsm_x4_t(bSt + kk * (16 * F2_BS * 2),      t0[0], t0[1], t0[2], t0[3]);
            ldsm_x4_t(bSt + kk * (16 * F2_BS * 2) + 32, t1[0], t1[1], t1[2], t1[3]);
            mma16816(acc[0][0], a0[0], a0[1], a0[2], a0[3], t0[0], t0[1]);
            mma16816(acc[0][1], a0[0], a0[1], a0[2], a0[3], t0[2], t0[3]);
            mma16816(acc[0][2], a0[0], a0[1], a0[2], a0[3], t1[0], t1[1]);
            mma16816(acc[0][3], a0[0], a0[1], a0[2], a0[3], t1[2], t1[3]);
            mma16816(acc[1][0], a1[0], a1[1], a1[2], a1[3], t0[0], t0[1]);
            mma16816(acc[1][1], a1[0], a1[1], a1[2], a1[3], t0[2], t0[3]);
            mma16816(acc[1][2], a1[0], a1[1], a1[2], a1[3], t1[0], t1[1]);
            mma16816(acc[1][3], a1[0], a1[1], a1[2], a1[3], t1[2], t1[3]);
        }
        stW = (stW == 2) ? 0 : stW + 1;
        stM = (stM == 2) ? 0 : stM + 1;
        stC = (stC == 2) ? 0 : stC + 1;
    }

    int erow = lane >> 2;
    int ecol = 2 * (lane & 3);
#pragma unroll
    for (int i = 0; i < 2; i++) {
#pragma unroll
        for (int j = 0; j < 4; j++) {
            int c = wn * 32 + j * 8 + ecol;
            if (c < NC) {
                int r_lo = row0 + wm * 32 + i * 16 + erow;
                *reinterpret_cast<float2*>(out + (size_t)r_lo * NC + c) =
                    make_float2(acc[i][j][0], acc[i][j][1]);
                *reinterpret_cast<float2*>(out + (size_t)(r_lo + 8) * NC + c) =
                    make_float2(acc[i][j][2], acc[i][j][3]);
            }
        }
    }
}

// -------- launch --------
extern "C" void kernel_launch(void* const* d_in, const int* in_sizes, int n_in,
                              void* d_out, int out_size) {
    const float* feat = nullptr;
    const float* mask = nullptr;
    const float* W    = nullptr;
    const float* bias = nullptr;
    const float* pi   = nullptr;
    for (int i = 0; i < n_in; i++) {
        switch (in_sizes[i]) {
            case BB * NF: feat = (const float*)d_in[i]; break;
            case NU * NF: mask = (const float*)d_in[i]; break;
            case NU * NL: W    = (const float*)d_in[i]; break;
            case NL:      bias = (const float*)d_in[i]; break;
            case NL * NC: pi   = (const float*)d_in[i]; break;
            default: break;
        }
    }
    if (!feat && n_in > 0) feat = (const float*)d_in[0];
    if (!mask && n_in > 1) mask = (const float*)d_in[1];
    if (!W    && n_in > 2) W    = (const float*)d_in[2];
    if (!bias && n_in > 3) bias = (const float*)d_in[3];
    if (!pi   && n_in > 4) pi   = (const float*)d_in[4];

    cudaFuncSetAttribute(k_gemm1,  cudaFuncAttributeMaxDynamicSharedMemorySize, G1_SMEM);
    cudaFuncSetAttribute(k_fused2, cudaFuncAttributeMaxDynamicSharedMemorySize, F2_SMEM);

    k_prep<<<640, 256>>>(W, pi, mask);
    k_gather<<<BB / 4, 256>>>(feat);
    k_gemm1<<<dim3(NL / 128, BB / 64), 256, G1_SMEM>>>(bias);
    k_fused2<<<BB / 64, 256, F2_SMEM>>>((float*)d_out);
    (void)out_size;
}